// round 1
// baseline (speedup 1.0000x reference)
#include <cuda_runtime.h>

// WindowAttention fused SIMT fp32 baseline.
// 1 CTA per window (8192 CTAs, 256 threads). All intermediates in SMEM.
//
// Per-CTA flow:
//   P0: load x[64x256], mask[64x64], rel_idx[64x64] to SMEM
//   per head h (8):
//     P1: QKV_h[64x96] = x @ W_h^T + b_h   (W_h = 32 rows of wq + 32 k-rows + 32 v-rows of wkv)
//     P2: S[64x64] = Q_h K_h^T
//     P3: softmax rows with SCALE, rel-pos bias gather, window mask
//     P4: O_h[64x32] = P V_h  -> Obuf[:, h*32:(h+1)*32]
//   P5: out[64x256] = Obuf @ wp^T + bp

#define NTOK   64
#define CDIM   256
#define HEADS  8
#define HDIM   32
#define NWIN   4096
#define ATTN_SCALE 0.17677669529663687f   // 32^-0.5

// SMEM float offsets / pitches (bank-conflict tuned)
#define XS_PITCH 260
#define OB_PITCH 260
#define WS_PITCH 33
#define QK_PITCH 101
#define SS_PITCH 66
#define MK_PITCH 65
#define RI_PITCH 65

#define XS_OFF 0
#define OB_OFF (XS_OFF + 64 * XS_PITCH)
#define WS_OFF (OB_OFF + 64 * OB_PITCH)
#define QK_OFF (WS_OFF + 128 * WS_PITCH)
#define SS_OFF (QK_OFF + 64 * QK_PITCH)
#define MK_OFF (SS_OFF + 64 * SS_PITCH)
#define RI_OFF (MK_OFF + 64 * MK_PITCH)
#define SMEM_FLOATS (RI_OFF + 64 * RI_PITCH)
#define SMEM_BYTES  (SMEM_FLOATS * 4)

__global__ __launch_bounds__(256, 1)
void winattn_kernel(const float* __restrict__ x,
                    const float* __restrict__ mask,
                    const float* __restrict__ wq,  const float* __restrict__ bq,
                    const float* __restrict__ wkv, const float* __restrict__ bkv,
                    const float* __restrict__ wp,  const float* __restrict__ bp,
                    const float* __restrict__ btab,
                    const int*   __restrict__ ridx,
                    float* __restrict__ out)
{
    extern __shared__ float sm[];
    float* xs = sm + XS_OFF;   // x window       [64][260]
    float* ob = sm + OB_OFF;   // attention out  [64][260]
    float* ws = sm + WS_OFF;   // weight k-chunk [128][33]
    float* qk = sm + QK_OFF;   // q|k|v head     [64][101]
    float* ss = sm + SS_OFF;   // scores/probs   [64][66]
    float* mk = sm + MK_OFF;   // window mask    [64][65]
    int*   ri = (int*)(sm + RI_OFF); // rel idx  [64][65]

    const int tid = threadIdx.x;
    const int b   = blockIdx.x;
    const int ty  = tid >> 4;   // 0..15
    const int tx  = tid & 15;   // 0..15

    // ---------- P0: stage inputs ----------
    const float4* x4 = (const float4*)(x + (size_t)b * NTOK * CDIM);
    for (int i = tid; i < NTOK * (CDIM / 4); i += 256) {
        int t = i >> 6, c4 = i & 63;
        float4 v = x4[i];
        float* d = xs + t * XS_PITCH + c4 * 4;
        d[0] = v.x; d[1] = v.y; d[2] = v.z; d[3] = v.w;
    }
    const float* mrow = mask + (size_t)(b & (NWIN - 1)) * NTOK * NTOK;
    for (int i = tid; i < NTOK * NTOK; i += 256) {
        int n = i >> 6, m = i & 63;
        mk[n * MK_PITCH + m] = mrow[i];
        ri[n * RI_PITCH + m] = ridx[i];
    }
    __syncthreads();

    // ---------- per-head loop ----------
    for (int h = 0; h < HEADS; h++) {
        // ---- P1: QKV_h = x @ W_h^T ----
        float acc[4][6];
        #pragma unroll
        for (int i = 0; i < 4; i++)
            #pragma unroll
            for (int j = 0; j < 6; j++) acc[i][j] = 0.f;

        for (int kc = 0; kc < 8; kc++) {
            __syncthreads();   // prior consumers of ws done
            for (int i = tid; i < 96 * 32; i += 256) {
                int r = i >> 5, kk = i & 31;
                const float* wrow;
                if (r < 32)      wrow = wq  + (size_t)(h * HDIM + r) * CDIM;
                else if (r < 64) wrow = wkv + (size_t)(h * HDIM + r - 32) * CDIM;
                else             wrow = wkv + (size_t)(CDIM + h * HDIM + r - 64) * CDIM;
                ws[r * WS_PITCH + kk] = wrow[kc * 32 + kk];
            }
            __syncthreads();
            #pragma unroll 4
            for (int kk = 0; kk < 32; kk++) {
                float a[4], bb[6];
                #pragma unroll
                for (int i = 0; i < 4; i++)
                    a[i] = xs[(ty * 4 + i) * XS_PITCH + kc * 32 + kk];
                #pragma unroll
                for (int j = 0; j < 6; j++)
                    bb[j] = ws[(tx * 6 + j) * WS_PITCH + kk];
                #pragma unroll
                for (int i = 0; i < 4; i++)
                    #pragma unroll
                    for (int j = 0; j < 6; j++)
                        acc[i][j] = fmaf(a[i], bb[j], acc[i][j]);
            }
        }
        // write q|k|v (+bias) into qk
        #pragma unroll
        for (int j = 0; j < 6; j++) {
            int o = tx * 6 + j;
            float bias;
            if (o < 32)      bias = __ldg(bq  + h * HDIM + o);
            else if (o < 64) bias = __ldg(bkv + h * HDIM + o - 32);
            else             bias = __ldg(bkv + CDIM + h * HDIM + o - 64);
            #pragma unroll
            for (int i = 0; i < 4; i++)
                qk[(ty * 4 + i) * QK_PITCH + o] = acc[i][j] + bias;
        }
        __syncthreads();

        // ---- P2: scores S = Q K^T ----
        {
            float sc[4][4];
            #pragma unroll
            for (int i = 0; i < 4; i++)
                #pragma unroll
                for (int j = 0; j < 4; j++) sc[i][j] = 0.f;
            #pragma unroll 4
            for (int d = 0; d < 32; d++) {
                float a[4], bb[4];
                #pragma unroll
                for (int i = 0; i < 4; i++)
                    a[i] = qk[(ty * 4 + i) * QK_PITCH + d];
                #pragma unroll
                for (int j = 0; j < 4; j++)
                    bb[j] = qk[(tx * 4 + j) * QK_PITCH + 32 + d];
                #pragma unroll
                for (int i = 0; i < 4; i++)
                    #pragma unroll
                    for (int j = 0; j < 4; j++)
                        sc[i][j] = fmaf(a[i], bb[j], sc[i][j]);
            }
            #pragma unroll
            for (int i = 0; i < 4; i++)
                #pragma unroll
                for (int j = 0; j < 4; j++)
                    ss[(ty * 4 + i) * SS_PITCH + tx * 4 + j] = sc[i][j];
        }
        __syncthreads();

        // ---- P3: softmax rows (scale + bias + mask) ----
        if (tid < 64) {
            int n = tid;
            float*       srow = ss + n * SS_PITCH;
            const float* mrw  = mk + n * MK_PITCH;
            const int*   rrw  = ri + n * RI_PITCH;
            float mx = -1e30f;
            #pragma unroll 8
            for (int m = 0; m < 64; m++) {
                float v = fmaf(srow[m], ATTN_SCALE,
                               __ldg(btab + rrw[m] * HEADS + h) + mrw[m]);
                srow[m] = v;
                mx = fmaxf(mx, v);
            }
            float s = 0.f;
            #pragma unroll 8
            for (int m = 0; m < 64; m++) {
                float p = __expf(srow[m] - mx);
                srow[m] = p;
                s += p;
            }
            float inv = 1.f / s;
            #pragma unroll 8
            for (int m = 0; m < 64; m++)
                srow[m] *= inv;
        }
        __syncthreads();

        // ---- P4: O_h = P @ V_h ----
        {
            int n  = tid >> 2;
            int d0 = (tid & 3) * 8;
            float av[8];
            #pragma unroll
            for (int j = 0; j < 8; j++) av[j] = 0.f;
            #pragma unroll 4
            for (int k = 0; k < 64; k++) {
                float p = ss[n * SS_PITCH + k];
                #pragma unroll
                for (int j = 0; j < 8; j++)
                    av[j] = fmaf(p, qk[k * QK_PITCH + 64 + d0 + j], av[j]);
            }
            #pragma unroll
            for (int j = 0; j < 8; j++)
                ob[n * OB_PITCH + h * HDIM + d0 + j] = av[j];
        }
        __syncthreads();
    }

    // ---------- P5: out = Obuf @ wp^T + bp ----------
    for (int oc = 0; oc < 2; oc++) {
        float acc2[4][8];
        #pragma unroll
        for (int i = 0; i < 4; i++)
            #pragma unroll
            for (int j = 0; j < 8; j++) acc2[i][j] = 0.f;

        for (int kc = 0; kc < 8; kc++) {
            __syncthreads();
            for (int i = tid; i < 128 * 32; i += 256) {
                int r = i >> 5, kk = i & 31;
                ws[r * WS_PITCH + kk] = wp[(size_t)(oc * 128 + r) * CDIM + kc * 32 + kk];
            }
            __syncthreads();
            #pragma unroll 4
            for (int kk = 0; kk < 32; kk++) {
                float a[4], bb[8];
                #pragma unroll
                for (int i = 0; i < 4; i++)
                    a[i] = ob[(ty * 4 + i) * OB_PITCH + kc * 32 + kk];
                #pragma unroll
                for (int j = 0; j < 8; j++)
                    bb[j] = ws[(tx + j * 16) * WS_PITCH + kk];
                #pragma unroll
                for (int i = 0; i < 4; i++)
                    #pragma unroll
                    for (int j = 0; j < 8; j++)
                        acc2[i][j] = fmaf(a[i], bb[j], acc2[i][j]);
            }
        }
        float* orow = out + (size_t)b * NTOK * CDIM;
        #pragma unroll
        for (int j = 0; j < 8; j++) {
            int c = oc * 128 + tx + j * 16;
            float bias = __ldg(bp + c);
            #pragma unroll
            for (int i = 0; i < 4; i++)
                orow[(ty * 4 + i) * CDIM + c] = acc2[i][j] + bias;
        }
    }
}

extern "C" void kernel_launch(void* const* d_in, const int* in_sizes, int n_in,
                              void* d_out, int out_size)
{
    const float* x    = (const float*)d_in[0];
    const float* mask = (const float*)d_in[1];
    const float* wq   = (const float*)d_in[2];
    const float* bq   = (const float*)d_in[3];
    const float* wkv  = (const float*)d_in[4];
    const float* bkv  = (const float*)d_in[5];
    const float* wp   = (const float*)d_in[6];
    const float* bp   = (const float*)d_in[7];
    const float* bt   = (const float*)d_in[8];
    const int*   ri   = (const int*)d_in[9];
    float* out = (float*)d_out;

    cudaFuncSetAttribute(winattn_kernel,
                         cudaFuncAttributeMaxDynamicSharedMemorySize, SMEM_BYTES);
    winattn_kernel<<<8192, 256, SMEM_BYTES>>>(x, mask, wq, bq, wkv, bkv, wp, bp, bt, ri, out);
}